// round 2
// baseline (speedup 1.0000x reference)
#include <cuda_runtime.h>
#include <cstdint>
#include <cstddef>

// Problem constants
#define BATCH  4
#define NSEQ   2048
#define DMODEL 1024
#define NHEAD  16
#define DKH    64
#define MROWS  (BATCH * NSEQ)   // 8192
#define NEGVAL (-1e11f)

// ---------------- scratch (device globals; no allocation allowed) ----------
__device__ float    g_Q[BATCH * NHEAD * NSEQ * DKH];   // (B,H,N,DK)
__device__ float    g_K[BATCH * NHEAD * NSEQ * DKH];
__device__ float    g_V[BATCH * NHEAD * NSEQ * DKH];
__device__ float    g_C[BATCH * NSEQ * DMODEL];        // attention context (B,N,D)
__device__ unsigned g_pmask[BATCH * NSEQ * NSEQ / 32]; // bit-packed mask

// ---------------- mask bit-pack: 67MB int32 -> 2MB bits --------------------
__global__ void pack_mask_kernel(const int* __restrict__ mask) {
    int idx = blockIdx.x * blockDim.x + threadIdx.x;
    unsigned bit = (mask[idx] != 0) ? 1u : 0u;
    unsigned w = __ballot_sync(0xffffffffu, bit);
    if ((threadIdx.x & 31) == 0) g_pmask[idx >> 5] = w;
}

// ---------------- SGEMM: C(8192x1024) = A @ W + bias -----------------------
// 128x128 tile, BK=8, 256 threads, 8x8 per thread.
// SPLIT=true remaps output to (B,H,N,DK) for attention.
template <bool SPLIT>
__global__ __launch_bounds__(256)
void sgemm_kernel(const float* __restrict__ A, const float* __restrict__ W,
                  const float* __restrict__ bias, float* __restrict__ out) {
    const int K = DMODEL, Nn = DMODEL;
    __shared__ float As[8][128];   // [k][m]
    __shared__ float Bs[8][128];   // [k][n]

    int tid = threadIdx.x;
    int tx = tid & 15, ty = tid >> 4;
    int m0 = blockIdx.y * 128, n0 = blockIdx.x * 128;

    int aRow = tid >> 1, aK = (tid & 1) * 4;
    int bRow = tid >> 5, bCol = (tid & 31) * 4;
    const float* Ap = A + (m0 + aRow) * K + aK;
    const float* Bp = W + bRow * Nn + n0 + bCol;

    float acc[8][8];
#pragma unroll
    for (int i = 0; i < 8; ++i)
#pragma unroll
        for (int j = 0; j < 8; ++j) acc[i][j] = 0.f;

    for (int kt = 0; kt < K; kt += 8) {
        float4 av = *(const float4*)(Ap + kt);
        float4 bv = *(const float4*)(Bp + kt * Nn);
        As[aK + 0][aRow] = av.x;
        As[aK + 1][aRow] = av.y;
        As[aK + 2][aRow] = av.z;
        As[aK + 3][aRow] = av.w;
        *(float4*)&Bs[bRow][bCol] = bv;
        __syncthreads();
#pragma unroll
        for (int k = 0; k < 8; ++k) {
            float ra[8], rb[8];
            *(float4*)&ra[0] = *(const float4*)&As[k][ty * 8];
            *(float4*)&ra[4] = *(const float4*)&As[k][ty * 8 + 4];
            *(float4*)&rb[0] = *(const float4*)&Bs[k][tx * 8];
            *(float4*)&rb[4] = *(const float4*)&Bs[k][tx * 8 + 4];
#pragma unroll
            for (int i = 0; i < 8; ++i)
#pragma unroll
                for (int j = 0; j < 8; ++j)
                    acc[i][j] += ra[i] * rb[j];
        }
        __syncthreads();
    }

    float rbias[8];
#pragma unroll
    for (int j = 0; j < 8; ++j) rbias[j] = __ldg(&bias[n0 + tx * 8 + j]);

#pragma unroll
    for (int i = 0; i < 8; ++i) {
        int m = m0 + ty * 8 + i;
#pragma unroll
        for (int j4 = 0; j4 < 8; j4 += 4) {
            int n = n0 + tx * 8 + j4;
            float4 v;
            v.x = acc[i][j4 + 0] + rbias[j4 + 0];
            v.y = acc[i][j4 + 1] + rbias[j4 + 1];
            v.z = acc[i][j4 + 2] + rbias[j4 + 2];
            v.w = acc[i][j4 + 3] + rbias[j4 + 3];
            size_t idx;
            if (SPLIT) {
                int b = m >> 11, row = m & 2047;
                int h = n >> 6, dk = n & 63;
                idx = (((size_t)(b * NHEAD + h) * NSEQ + row) * DKH + dk);
            } else {
                idx = (size_t)m * Nn + n;
            }
            *(float4*)&out[idx] = v;
        }
    }
}

// ---------------- fused masked flash attention -----------------------------
// grid: (N/64, B*H), block 256.  64-query tile, stream K/V in 64-key tiles.
// smem tiles padded to 68 floats/row to keep LDS vector reads low-conflict.
__global__ __launch_bounds__(256)
void attn_kernel() {
    extern __shared__ float sm[];
    float* Qs = sm;              // [d=64][row 68]   (transposed)
    float* Ks = Qs + 64 * 68;    // [d=64][col 68]   (transposed)
    float* Vs = Ks + 64 * 68;    // [k=64][dk 68]    (natural)
    float* Ps = Vs + 64 * 68;    // [row=64][k 68]

    int tid = threadIdx.x;
    int tx = tid & 15, ty = tid >> 4;
    int bh = blockIdx.y;
    int b = bh >> 4, h = bh & 15;
    int q0 = blockIdx.x * 64;

    const float* Qg = g_Q + ((size_t)bh * NSEQ + q0) * DKH;
    const float* Kg = g_K + (size_t)bh * NSEQ * DKH;
    const float* Vg = g_V + (size_t)bh * NSEQ * DKH;

    // Load Q tile transposed: Qs[d][row]
#pragma unroll
    for (int i = 0; i < 4; ++i) {
        int f = tid + 256 * i;
        int row = f >> 4, d0 = (f & 15) * 4;
        float4 q = *(const float4*)(Qg + row * DKH + d0);
        Qs[(d0 + 0) * 68 + row] = q.x;
        Qs[(d0 + 1) * 68 + row] = q.y;
        Qs[(d0 + 2) * 68 + row] = q.z;
        Qs[(d0 + 3) * 68 + row] = q.w;
    }

    float m_run[4], l_run[4], o[4][4];
#pragma unroll
    for (int i = 0; i < 4; ++i) {
        m_run[i] = -1e30f;
        l_run[i] = 0.f;
#pragma unroll
        for (int j = 0; j < 4; ++j) o[i][j] = 0.f;
    }

    const int maskRowBase = b * NSEQ + q0;

    for (int kt = 0; kt < NSEQ / 64; ++kt) {
        __syncthreads();  // previous iteration done reading Ks/Vs
        // Load K transposed + V natural
#pragma unroll
        for (int i = 0; i < 4; ++i) {
            int f = tid + 256 * i;
            int row = f >> 4, d0 = (f & 15) * 4;
            float4 kv = *(const float4*)(Kg + (size_t)(kt * 64 + row) * DKH + d0);
            Ks[(d0 + 0) * 68 + row] = kv.x;
            Ks[(d0 + 1) * 68 + row] = kv.y;
            Ks[(d0 + 2) * 68 + row] = kv.z;
            Ks[(d0 + 3) * 68 + row] = kv.w;
            float4 vv = *(const float4*)(Vg + (size_t)(kt * 64 + row) * DKH + d0);
            *(float4*)&Vs[row * 68 + d0] = vv;
        }
        __syncthreads();

        // S = Q @ K^T  (each thread: rows 4ty..+3, cols 4tx..+3)
        float s[4][4];
#pragma unroll
        for (int i = 0; i < 4; ++i)
#pragma unroll
            for (int j = 0; j < 4; ++j) s[i][j] = 0.f;

#pragma unroll 8
        for (int d = 0; d < 64; ++d) {
            float qa[4], kb[4];
            *(float4*)qa = *(const float4*)&Qs[d * 68 + 4 * ty];
            *(float4*)kb = *(const float4*)&Ks[d * 68 + 4 * tx];
#pragma unroll
            for (int i = 0; i < 4; ++i)
#pragma unroll
                for (int j = 0; j < 4; ++j)
                    s[i][j] += qa[i] * kb[j];
        }

        // scale + mask + online softmax (row = 16 lanes of this warp half)
        int wcol = kt * 2 + (tx >> 3);
        int bit0 = (4 * tx) & 31;
#pragma unroll
        for (int i = 0; i < 4; ++i) {
            unsigned mw = g_pmask[(size_t)(maskRowBase + 4 * ty + i) * (NSEQ / 32) + wcol];
            float rm = -1e30f;
#pragma unroll
            for (int j = 0; j < 4; ++j) {
                float v = ((mw >> (bit0 + j)) & 1u) ? s[i][j] * 0.125f : NEGVAL;
                s[i][j] = v;
                rm = fmaxf(rm, v);
            }
#pragma unroll
            for (int off = 8; off; off >>= 1)
                rm = fmaxf(rm, __shfl_xor_sync(0xffffffffu, rm, off));
            float mn = fmaxf(m_run[i], rm);
            float corr = __expf(m_run[i] - mn);
            m_run[i] = mn;
            float p[4];
            float ls = 0.f;
#pragma unroll
            for (int j = 0; j < 4; ++j) {
                p[j] = __expf(s[i][j] - mn);
                ls += p[j];
            }
#pragma unroll
            for (int off = 8; off; off >>= 1)
                ls += __shfl_xor_sync(0xffffffffu, ls, off);
            l_run[i] = l_run[i] * corr + ls;
#pragma unroll
            for (int j = 0; j < 4; ++j) o[i][j] *= corr;
            *(float4*)&Ps[(4 * ty + i) * 68 + 4 * tx] = make_float4(p[0], p[1], p[2], p[3]);
        }
        __syncthreads();

        // O += P @ V
#pragma unroll 4
        for (int k4 = 0; k4 < 64; k4 += 4) {
            float pr[4][4];
#pragma unroll
            for (int i = 0; i < 4; ++i)
                *(float4*)pr[i] = *(const float4*)&Ps[(4 * ty + i) * 68 + k4];
#pragma unroll
            for (int kk = 0; kk < 4; ++kk) {
                float vv[4];
                *(float4*)vv = *(const float4*)&Vs[(k4 + kk) * 68 + 4 * tx];
#pragma unroll
                for (int i = 0; i < 4; ++i)
#pragma unroll
                    for (int j = 0; j < 4; ++j)
                        o[i][j] += pr[i][kk] * vv[j];
            }
        }
    }

    // normalize + write context in (B,N,D) layout for the output projection
    float* Cg = g_C + ((size_t)(b * NSEQ + q0)) * DMODEL + h * DKH;
#pragma unroll
    for (int i = 0; i < 4; ++i) {
        float inv = 1.0f / l_run[i];
        float4 v = make_float4(o[i][0] * inv, o[i][1] * inv, o[i][2] * inv, o[i][3] * inv);
        *(float4*)&Cg[(size_t)(4 * ty + i) * DMODEL + 4 * tx] = v;
    }
}

// ---------------- launch ----------------------------------------------------
extern "C" void kernel_launch(void* const* d_in, const int* in_sizes, int n_in,
                              void* d_out, int out_size) {
    const float* query = (const float*)d_in[0];
    const float* key   = (const float*)d_in[1];
    const float* value = (const float*)d_in[2];
    const int*   mask  = (const int*)d_in[3];
    const float* Wq = (const float*)d_in[4];
    const float* bq = (const float*)d_in[5];
    const float* Wk = (const float*)d_in[6];
    const float* bk = (const float*)d_in[7];
    const float* Wv = (const float*)d_in[8];
    const float* bv = (const float*)d_in[9];
    const float* Wo = (const float*)d_in[10];
    const float* bo = (const float*)d_in[11];
    float* out = (float*)d_out;

    float *pQ, *pK, *pV, *pC;
    cudaGetSymbolAddress((void**)&pQ, g_Q);
    cudaGetSymbolAddress((void**)&pK, g_K);
    cudaGetSymbolAddress((void**)&pV, g_V);
    cudaGetSymbolAddress((void**)&pC, g_C);

    // 1) pack mask to bits (L2-resident afterwards)
    pack_mask_kernel<<<(BATCH * NSEQ * NSEQ) / 256, 256>>>(mask);

    // 2) Q/K/V projections, written directly in (B,H,N,DK)
    dim3 gg(DMODEL / 128, MROWS / 128);
    sgemm_kernel<true><<<gg, 256>>>(query, Wq, bq, pQ);
    sgemm_kernel<true><<<gg, 256>>>(key,   Wk, bk, pK);
    sgemm_kernel<true><<<gg, 256>>>(value, Wv, bv, pV);

    // 3) fused masked attention
    const int attn_smem = 4 * 64 * 68 * (int)sizeof(float);  // 69632
    cudaFuncSetAttribute(attn_kernel, cudaFuncAttributeMaxDynamicSharedMemorySize,
                         attn_smem);
    attn_kernel<<<dim3(NSEQ / 64, BATCH * NHEAD), 256, attn_smem>>>();

    // 4) output projection -> d_out
    sgemm_kernel<false><<<gg, 256>>>(pC, Wo, bo, out);
}

// round 3
// speedup vs baseline: 1.5413x; 1.5413x over previous
#include <cuda_runtime.h>
#include <cstdint>
#include <cstddef>

// Problem constants
#define BATCH  4
#define NSEQ   2048
#define DMODEL 1024
#define NHEAD  16
#define DKH    64
#define MROWS  (BATCH * NSEQ)   // 8192
#define NEGVAL (-1e11f)

// ---------------- scratch (device globals; no allocation allowed) ----------
__device__ float    g_Q[BATCH * NHEAD * NSEQ * DKH];   // (B,H,N,DK)
__device__ float    g_K[BATCH * NHEAD * NSEQ * DKH];
__device__ float    g_V[BATCH * NHEAD * NSEQ * DKH];
__device__ float    g_C[BATCH * NSEQ * DMODEL];        // attention context (B,N,D)
__device__ unsigned g_pmask[BATCH * NSEQ * NSEQ / 32]; // bit-packed mask

// ---------------- helpers ---------------------------------------------------
__device__ __forceinline__ uint32_t f2tf32(float x) {
    uint32_t r;
    asm("cvt.rna.tf32.f32 %0, %1;" : "=r"(r) : "f"(x));
    return r;
}

__device__ __forceinline__ void mma_tf32(float* c, const uint32_t* a,
                                         uint32_t b0, uint32_t b1) {
    asm volatile(
        "mma.sync.aligned.m16n8k8.row.col.f32.tf32.tf32.f32 "
        "{%0,%1,%2,%3}, {%4,%5,%6,%7}, {%8,%9}, {%0,%1,%2,%3};"
        : "+f"(c[0]), "+f"(c[1]), "+f"(c[2]), "+f"(c[3])
        : "r"(a[0]), "r"(a[1]), "r"(a[2]), "r"(a[3]), "r"(b0), "r"(b1));
}

// ---------------- mask bit-pack: 67MB int32 -> 2MB bits --------------------
__global__ void pack_mask_kernel(const int* __restrict__ mask) {
    int idx = blockIdx.x * blockDim.x + threadIdx.x;
    unsigned bit = (mask[idx] != 0) ? 1u : 0u;
    unsigned w = __ballot_sync(0xffffffffu, bit);
    if ((threadIdx.x & 31) == 0) g_pmask[idx >> 5] = w;
}

// ---------------- projection GEMM: 3xTF32 mma.sync --------------------------
// C(8192x1024) = A @ W + bias.  Block tile 128x128, BK=16, 256 threads (8 warps,
// 2x4 warp grid, warp tile 64x32).  Split-precision: err ~ fp32.
template <bool SPLIT>
__global__ __launch_bounds__(256)
void proj_mma_kernel(const float* __restrict__ A, const float* __restrict__ W,
                     const float* __restrict__ bias, float* __restrict__ out) {
    __shared__ uint32_t AsH[16][136];   // [k][m] tf32-hi
    __shared__ uint32_t AsL[16][136];   // [k][m] tf32-lo
    __shared__ uint32_t BsH[16][136];   // [k][n]
    __shared__ uint32_t BsL[16][136];

    const int tid = threadIdx.x;
    const int w = tid >> 5, l = tid & 31;
    const int lg = l >> 2, lk = l & 3;
    const int wm = (w >> 2) * 64;       // 0,64
    const int wn = (w & 3) * 32;        // 0,32,64,96
    const int m0 = blockIdx.y * 128, n0 = blockIdx.x * 128;

    float c[4][4][4];
#pragma unroll
    for (int mi = 0; mi < 4; ++mi)
#pragma unroll
        for (int nj = 0; nj < 4; ++nj)
#pragma unroll
            for (int t = 0; t < 4; ++t) c[mi][nj][t] = 0.f;

    for (int kt = 0; kt < DMODEL; kt += 16) {
        // prefetch to registers
        float4 av[2], bv[2];
#pragma unroll
        for (int i = 0; i < 2; ++i) {
            int v = tid + 256 * i;
            int am = v & 127, ak4 = (v >> 7) * 4;            // A: row am, k ak4..+3
            av[i] = *(const float4*)(A + (size_t)(m0 + am) * DMODEL + kt + ak4);
            int bk = v >> 5, bn4 = (v & 31) * 4;             // B: row bk, n bn4..+3
            bv[i] = *(const float4*)(W + (size_t)(kt + bk) * DMODEL + n0 + bn4);
        }
        __syncthreads();   // previous tile fully consumed
#pragma unroll
        for (int i = 0; i < 2; ++i) {
            int v = tid + 256 * i;
            int am = v & 127, ak4 = (v >> 7) * 4;
            const float* af = (const float*)&av[i];
#pragma unroll
            for (int j = 0; j < 4; ++j) {
                uint32_t hi = f2tf32(af[j]);
                AsH[ak4 + j][am] = hi;
                AsL[ak4 + j][am] = f2tf32(af[j] - __uint_as_float(hi));
            }
            int bk = v >> 5, bn4 = (v & 31) * 4;
            const float* bf = (const float*)&bv[i];
#pragma unroll
            for (int j = 0; j < 4; ++j) {
                uint32_t hi = f2tf32(bf[j]);
                BsH[bk][bn4 + j] = hi;
                BsL[bk][bn4 + j] = f2tf32(bf[j] - __uint_as_float(hi));
            }
        }
        __syncthreads();

#pragma unroll
        for (int ks = 0; ks < 16; ks += 8) {
            uint32_t aH[4][4], aL[4][4];
#pragma unroll
            for (int mi = 0; mi < 4; ++mi) {
                int mbase = wm + 16 * mi + lg;
                aH[mi][0] = AsH[ks + lk][mbase];
                aH[mi][1] = AsH[ks + lk][mbase + 8];
                aH[mi][2] = AsH[ks + lk + 4][mbase];
                aH[mi][3] = AsH[ks + lk + 4][mbase + 8];
                aL[mi][0] = AsL[ks + lk][mbase];
                aL[mi][1] = AsL[ks + lk][mbase + 8];
                aL[mi][2] = AsL[ks + lk + 4][mbase];
                aL[mi][3] = AsL[ks + lk + 4][mbase + 8];
            }
#pragma unroll
            for (int nj = 0; nj < 4; ++nj) {
                int nb = wn + 8 * nj + lg;
                uint32_t bH0 = BsH[ks + lk][nb], bH1 = BsH[ks + lk + 4][nb];
                uint32_t bL0 = BsL[ks + lk][nb], bL1 = BsL[ks + lk + 4][nb];
#pragma unroll
                for (int mi = 0; mi < 4; ++mi) {
                    mma_tf32(c[mi][nj], aH[mi], bH0, bH1);
                    mma_tf32(c[mi][nj], aH[mi], bL0, bL1);
                    mma_tf32(c[mi][nj], aL[mi], bH0, bH1);
                }
            }
        }
    }

    // epilogue: bias + store (optionally remapped to (B,H,N,DK))
#pragma unroll
    for (int mi = 0; mi < 4; ++mi) {
#pragma unroll
        for (int nj = 0; nj < 4; ++nj) {
            int col = n0 + wn + 8 * nj + 2 * lk;
            float b0 = __ldg(&bias[col]), b1 = __ldg(&bias[col + 1]);
#pragma unroll
            for (int half = 0; half < 2; ++half) {
                int m = m0 + wm + 16 * mi + lg + 8 * half;
                float2 v;
                v.x = c[mi][nj][2 * half + 0] + b0;
                v.y = c[mi][nj][2 * half + 1] + b1;
                size_t idx;
                if (SPLIT) {
                    int b = m >> 11, row = m & 2047;
                    int h = col >> 6, dk = col & 63;
                    idx = (((size_t)(b * NHEAD + h) * NSEQ + row) * DKH + dk);
                } else {
                    idx = (size_t)m * DMODEL + col;
                }
                *(float2*)&out[idx] = v;
            }
        }
    }
}

// ---------------- fused masked flash attention (tf32 mma) -------------------
// grid: (N/64, B*H), block 256 (8 warps).  64-query tile, 64-key tiles.
// S = Q@K^T via mma -> smem; proven scalar softmax on smem; PV via mma.
#define QPAD 68
#define KPAD 72
__global__ __launch_bounds__(256)
void attn_kernel() {
    extern __shared__ char smraw[];
    uint32_t* Qs = (uint32_t*)smraw;                    // [64][QPAD] (q-major, tf32)
    uint32_t* Ks = (uint32_t*)(smraw + 64 * QPAD * 4);  // [64][KPAD] ([d][key], tf32)
    uint32_t* Vs = (uint32_t*)(smraw + 64 * QPAD * 4 + 64 * KPAD * 4); // [key][KPAD]
    float*    Ps = (float*)(smraw + 64 * QPAD * 4 + 2 * 64 * KPAD * 4); // [64][QPAD]
    float*    Cr = (float*)(smraw + 2 * 64 * QPAD * 4 + 2 * 64 * KPAD * 4); // [64]

    const int tid = threadIdx.x;
    const int w = tid >> 5, l = tid & 31;
    const int lg = l >> 2, lk = l & 3;
    const int rb = (w >> 1) * 16;       // warp row band
    const int cb = (w & 1) * 32;        // warp col half
    const int tx = tid & 15, ty = tid >> 4;
    const int bh = blockIdx.y;
    const int b = bh >> 4;
    const int h = bh & 15;
    const int q0 = blockIdx.x * 64;

    const float* Qg = g_Q + ((size_t)bh * NSEQ + q0) * DKH;
    const float* Kg = g_K + (size_t)bh * NSEQ * DKH;
    const float* Vg = g_V + (size_t)bh * NSEQ * DKH;

    // ---- load Q tile (rounded to tf32), q-major ----
#pragma unroll
    for (int i = 0; i < 4; ++i) {
        int v = tid + 256 * i;
        int row = v >> 4, d4 = (v & 15) * 4;
        float4 q = *(const float4*)(Qg + (size_t)row * DKH + d4);
        Qs[row * QPAD + d4 + 0] = f2tf32(q.x);
        Qs[row * QPAD + d4 + 1] = f2tf32(q.y);
        Qs[row * QPAD + d4 + 2] = f2tf32(q.z);
        Qs[row * QPAD + d4 + 3] = f2tf32(q.w);
    }
    __syncthreads();

    // preload Q fragments (rows rb..rb+15, all 8 k-steps)
    uint32_t qf[8][4];
#pragma unroll
    for (int ks = 0; ks < 8; ++ks) {
        qf[ks][0] = Qs[(rb + lg) * QPAD + ks * 8 + lk];
        qf[ks][1] = Qs[(rb + lg + 8) * QPAD + ks * 8 + lk];
        qf[ks][2] = Qs[(rb + lg) * QPAD + ks * 8 + lk + 4];
        qf[ks][3] = Qs[(rb + lg + 8) * QPAD + ks * 8 + lk + 4];
    }

    // softmax state (owned by the (tx,ty) view threads)
    float m_run[4], l_run[4];
#pragma unroll
    for (int i = 0; i < 4; ++i) { m_run[i] = -1e30f; l_run[i] = 0.f; }

    // PV accumulators (owned by the mma view threads)
    float o[4][4];
#pragma unroll
    for (int nj = 0; nj < 4; ++nj)
#pragma unroll
        for (int t = 0; t < 4; ++t) o[nj][t] = 0.f;

    const int maskRowBase = b * NSEQ + q0;

    for (int kt = 0; kt < NSEQ / 64; ++kt) {
        __syncthreads();   // prior iteration done with Ks/Vs/Ps
        // ---- fill K (transposed [d][key]) and V ([key][dk]), tf32 ----
#pragma unroll
        for (int i = 0; i < 4; ++i) {
            int v = tid + 256 * i;
            {   // K: conflict-free STS layout
                int key = v & 63, d4 = (v >> 6) * 4;
                float4 kv = *(const float4*)(Kg + (size_t)(kt * 64 + key) * DKH + d4);
                Ks[(d4 + 0) * KPAD + key] = f2tf32(kv.x);
                Ks[(d4 + 1) * KPAD + key] = f2tf32(kv.y);
                Ks[(d4 + 2) * KPAD + key] = f2tf32(kv.z);
                Ks[(d4 + 3) * KPAD + key] = f2tf32(kv.w);
            }
            {   // V: coalesced load, natural layout
                int key = v >> 4, d4 = (v & 15) * 4;
                float4 vv = *(const float4*)(Vg + (size_t)(kt * 64 + key) * DKH + d4);
                Vs[key * KPAD + d4 + 0] = f2tf32(vv.x);
                Vs[key * KPAD + d4 + 1] = f2tf32(vv.y);
                Vs[key * KPAD + d4 + 2] = f2tf32(vv.z);
                Vs[key * KPAD + d4 + 3] = f2tf32(vv.w);
            }
        }
        __syncthreads();

        // ---- S = Q @ K^T (mma), store to Ps ----
        {
            float sc[4][4];
#pragma unroll
            for (int nj = 0; nj < 4; ++nj)
#pragma unroll
                for (int t = 0; t < 4; ++t) sc[nj][t] = 0.f;
#pragma unroll
            for (int ks = 0; ks < 8; ++ks) {
#pragma unroll
                for (int nj = 0; nj < 4; ++nj) {
                    int nb = cb + 8 * nj + lg;
                    uint32_t b0 = Ks[(ks * 8 + lk) * KPAD + nb];
                    uint32_t b1 = Ks[(ks * 8 + lk + 4) * KPAD + nb];
                    mma_tf32(sc[nj], qf[ks], b0, b1);
                }
            }
#pragma unroll
            for (int nj = 0; nj < 4; ++nj) {
                int col = cb + 8 * nj + 2 * lk;
                *(float2*)&Ps[(rb + lg) * QPAD + col] = make_float2(sc[nj][0], sc[nj][1]);
                *(float2*)&Ps[(rb + lg + 8) * QPAD + col] = make_float2(sc[nj][2], sc[nj][3]);
            }
        }
        __syncthreads();

        // ---- scalar masked online softmax on Ps (proven round-0 logic) ----
        {
            int wcol = kt * 2 + (tx >> 3);
            int bit0 = (4 * tx) & 31;
#pragma unroll
            for (int i = 0; i < 4; ++i) {
                int row = 4 * ty + i;
                float4 sv = *(const float4*)&Ps[row * QPAD + 4 * tx];
                float s[4] = {sv.x, sv.y, sv.z, sv.w};
                unsigned mw = g_pmask[(size_t)(maskRowBase + row) * (NSEQ / 32) + wcol];
                float rm = -1e30f;
#pragma unroll
                for (int j = 0; j < 4; ++j) {
                    float vv = ((mw >> (bit0 + j)) & 1u) ? s[j] * 0.125f : NEGVAL;
                    s[j] = vv;
                    rm = fmaxf(rm, vv);
                }
#pragma unroll
                for (int off = 8; off; off >>= 1)
                    rm = fmaxf(rm, __shfl_xor_sync(0xffffffffu, rm, off));
                float mn = fmaxf(m_run[i], rm);
                float corr = __expf(m_run[i] - mn);
                m_run[i] = mn;
                float p[4], ls = 0.f;
#pragma unroll
                for (int j = 0; j < 4; ++j) {
                    p[j] = __uint_as_float(f2tf32(__expf(s[j] - mn)));
                    ls += p[j];
                }
#pragma unroll
                for (int off = 8; off; off >>= 1)
                    ls += __shfl_xor_sync(0xffffffffu, ls, off);
                l_run[i] = l_run[i] * corr + ls;
                *(float4*)&Ps[row * QPAD + 4 * tx] = make_float4(p[0], p[1], p[2], p[3]);
                if (tx == 0) Cr[row] = corr;
            }
        }
        __syncthreads();

        // ---- O = O*corr + P @ V (mma) ----
        {
            float cr0 = Cr[rb + lg], cr1 = Cr[rb + lg + 8];
#pragma unroll
            for (int nj = 0; nj < 4; ++nj) {
                o[nj][0] *= cr0; o[nj][1] *= cr0;
                o[nj][2] *= cr1; o[nj][3] *= cr1;
            }
#pragma unroll
            for (int ks = 0; ks < 8; ++ks) {
                uint32_t af[4];
                af[0] = __float_as_uint(Ps[(rb + lg) * QPAD + ks * 8 + lk]);
                af[1] = __float_as_uint(Ps[(rb + lg + 8) * QPAD + ks * 8 + lk]);
                af[2] = __float_as_uint(Ps[(rb + lg) * QPAD + ks * 8 + lk + 4]);
                af[3] = __float_as_uint(Ps[(rb + lg + 8) * QPAD + ks * 8 + lk + 4]);
#pragma unroll
                for (int nj = 0; nj < 4; ++nj) {
                    int nb = cb + 8 * nj + lg;
                    uint32_t b0 = Vs[(ks * 8 + lk) * KPAD + nb];
                    uint32_t b1 = Vs[(ks * 8 + lk + 4) * KPAD + nb];
                    mma_tf32(o[nj], af, b0, b1);
                }
            }
        }
    }

    // ---- normalize and write context ----
    __syncthreads();
#pragma unroll
    for (int i = 0; i < 4; ++i)
        if (tx == 0) Cr[4 * ty + i] = 1.0f / l_run[i];
    __syncthreads();

    float inv0 = Cr[rb + lg], inv1 = Cr[rb + lg + 8];
    float* Cg = g_C + ((size_t)(b * NSEQ + q0)) * DMODEL + h * DKH;
#pragma unroll
    for (int nj = 0; nj < 4; ++nj) {
        int col = cb + 8 * nj + 2 * lk;
        *(float2*)&Cg[(size_t)(rb + lg) * DMODEL + col] =
            make_float2(o[nj][0] * inv0, o[nj][1] * inv0);
        *(float2*)&Cg[(size_t)(rb + lg + 8) * DMODEL + col] =
            make_float2(o[nj][2] * inv1, o[nj][3] * inv1);
    }
}

// ---------------- launch ----------------------------------------------------
extern "C" void kernel_launch(void* const* d_in, const int* in_sizes, int n_in,
                              void* d_out, int out_size) {
    const float* query = (const float*)d_in[0];
    const float* key   = (const float*)d_in[1];
    const float* value = (const float*)d_in[2];
    const int*   mask  = (const int*)d_in[3];
    const float* Wq = (const float*)d_in[4];
    const float* bq = (const float*)d_in[5];
    const float* Wk = (const float*)d_in[6];
    const float* bk = (const float*)d_in[7];
    const float* Wv = (const float*)d_in[8];
    const float* bv = (const float*)d_in[9];
    const float* Wo = (const float*)d_in[10];
    const float* bo = (const float*)d_in[11];
    float* out = (float*)d_out;

    float *pQ, *pK, *pV, *pC;
    cudaGetSymbolAddress((void**)&pQ, g_Q);
    cudaGetSymbolAddress((void**)&pK, g_K);
    cudaGetSymbolAddress((void**)&pV, g_V);
    cudaGetSymbolAddress((void**)&pC, g_C);

    // 1) pack mask to bits
    pack_mask_kernel<<<(BATCH * NSEQ * NSEQ) / 256, 256>>>(mask);

    // 2) Q/K/V projections (3xTF32), written directly in (B,H,N,DK)
    dim3 gg(DMODEL / 128, MROWS / 128);
    proj_mma_kernel<true><<<gg, 256>>>(query, Wq, bq, pQ);
    proj_mma_kernel<true><<<gg, 256>>>(key,   Wk, bk, pK);
    proj_mma_kernel<true><<<gg, 256>>>(value, Wv, bv, pV);

    // 3) fused masked attention (tf32 mma)
    const int attn_smem = (2 * 64 * QPAD + 2 * 64 * KPAD) * 4 + 64 * 4; // 71936
    cudaFuncSetAttribute(attn_kernel, cudaFuncAttributeMaxDynamicSharedMemorySize,
                         attn_smem);
    attn_kernel<<<dim3(NSEQ / 64, BATCH * NHEAD), 256, attn_smem>>>();

    // 4) output projection (3xTF32) -> d_out
    proj_mma_kernel<false><<<gg, 256>>>(pC, Wo, bo, out);
}